// round 8
// baseline (speedup 1.0000x reference)
#include <cuda_runtime.h>
#include <stdint.h>

#define BATCH 16
#define NPTS  131072
#define NSAMP 1024
#define BPB   8                      // blocks per batch
#define PTS   (NPTS / BPB)           // 16384 points per block
#define TH    512                    // threads per block
#define NW    (TH / 32)              // 16 warps
#define ARRIVALS (BPB * NW)          // 128 warp-arrivals per batch per iter
#define KK    (PTS / (4 * TH))       // 8 x 4-point chunks per thread
#define SMEM_BYTES (PTS * 3 * (int)sizeof(float))   // 196608

#define OFF_SCALE (BATCH * NSAMP * 3)   // 49152
#define OFF_IDX   (OFF_SCALE + BATCH)   // 49168

typedef unsigned long long u64;
typedef unsigned int       u32;

// per-batch exchange cell: 4 key slots + arrival counter, one 128B line,
// 128B-aligned so different batches never share an LTS line
struct __align__(128) Exch { u64 key[4]; u32 cnt; u32 pad[23]; };

__device__ Exch  g_ex[BATCH];
__device__ int   g_idx[BATCH * NSAMP];
__device__ float g_scale[BATCH];
__device__ float g_psum[BATCH][BPB][3];
__device__ float g_pmax[BATCH][BPB];

// ---------------------------------------------------------------------------
// helpers
// ---------------------------------------------------------------------------
__device__ __forceinline__ u64 add2(u64 a, u64 b) {
    u64 d; asm("add.rn.f32x2 %0,%1,%2;" : "=l"(d) : "l"(a), "l"(b)); return d;
}
__device__ __forceinline__ u64 mul2(u64 a, u64 b) {
    u64 d; asm("mul.rn.f32x2 %0,%1,%2;" : "=l"(d) : "l"(a), "l"(b)); return d;
}
__device__ __forceinline__ void unpack2(u64 v, int& lo, int& hi) {
    asm("mov.b64 {%0,%1},%2;" : "=r"(lo), "=r"(hi) : "l"(v));
}
__device__ __forceinline__ u64 bcast2(float v) {
    u32 b = __float_as_uint(v); return ((u64)b << 32) | (u64)b;
}
__device__ __forceinline__ u32 ld_acq32(const u32* p) {
    u32 v; asm volatile("ld.acquire.gpu.global.u32 %0,[%1];" : "=r"(v) : "l"(p) : "memory");
    return v;
}
__device__ __forceinline__ u64 ld_acq64(const u64* p) {
    u64 v; asm volatile("ld.acquire.gpu.global.u64 %0,[%1];" : "=l"(v) : "l"(p) : "memory");
    return v;
}
__device__ __forceinline__ void st_zero64(u64* p) {
    asm volatile("st.relaxed.gpu.global.u64 [%0],0;" :: "l"(p) : "memory");
}
__device__ __forceinline__ void red_max64(u64* p, u64 v) {
    asm volatile("red.relaxed.gpu.global.max.u64 [%0],%1;" :: "l"(p), "l"(v) : "memory");
}
__device__ __forceinline__ void red_rel_add(u32* p, u32 v) {
    asm volatile("red.release.gpu.global.add.u32 [%0],%1;" :: "l"(p), "r"(v) : "memory");
}

// ---------------------------------------------------------------------------
// Scale pass 1: per-slice partial sums (deterministic tree)
// ---------------------------------------------------------------------------
__global__ void __launch_bounds__(512, 1)
scale1_kernel(const float* __restrict__ mesh)
{
    const int b = blockIdx.x / BPB, s = blockIdx.x % BPB, tid = threadIdx.x;
    const float* base = mesh + (size_t)b * NPTS * 3 + (size_t)s * PTS * 3;

    float sx = 0.f, sy = 0.f, sz = 0.f;
    for (int p = tid; p < PTS; p += 512) {
        const float* q = base + (size_t)p * 3;
        sx += q[0]; sy += q[1]; sz += q[2];
    }
    __shared__ float red[3][16];
    #pragma unroll
    for (int off = 16; off; off >>= 1) {
        sx += __shfl_xor_sync(0xffffffffu, sx, off);
        sy += __shfl_xor_sync(0xffffffffu, sy, off);
        sz += __shfl_xor_sync(0xffffffffu, sz, off);
    }
    const int w = tid >> 5, l = tid & 31;
    if (l == 0) { red[0][w] = sx; red[1][w] = sy; red[2][w] = sz; }
    __syncthreads();
    if (w == 0 && l < 16) {
        sx = red[0][l]; sy = red[1][l]; sz = red[2][l];
        #pragma unroll
        for (int off = 8; off; off >>= 1) {
            sx += __shfl_xor_sync(0xffffffffu, sx, off);
            sy += __shfl_xor_sync(0xffffffffu, sy, off);
            sz += __shfl_xor_sync(0xffffffffu, sz, off);
        }
        if (l == 0) {
            g_psum[b][s][0] = sx; g_psum[b][s][1] = sy; g_psum[b][s][2] = sz;
        }
    }
}

// ---------------------------------------------------------------------------
// Scale pass 2: finalize mean (fixed order), partial max of dist^2 per slice
// ---------------------------------------------------------------------------
__global__ void __launch_bounds__(512, 1)
scale2_kernel(const float* __restrict__ mesh)
{
    const int b = blockIdx.x / BPB, s = blockIdx.x % BPB, tid = threadIdx.x;

    float mx = 0.f, my = 0.f, mz = 0.f;
    #pragma unroll
    for (int i = 0; i < BPB; i++) {
        mx += g_psum[b][i][0]; my += g_psum[b][i][1]; mz += g_psum[b][i][2];
    }
    const float cx = mx * (1.0f / NPTS), cy = my * (1.0f / NPTS), cz = mz * (1.0f / NPTS);

    const float* base = mesh + (size_t)b * NPTS * 3 + (size_t)s * PTS * 3;
    float m = 0.f;
    for (int p = tid; p < PTS; p += 512) {
        const float* q = base + (size_t)p * 3;
        float dx = q[0] - cx, dy = q[1] - cy, dz = q[2] - cz;
        m = fmaxf(m, dx * dx + dy * dy + dz * dz);
    }
    __shared__ float red[16];
    #pragma unroll
    for (int off = 16; off; off >>= 1)
        m = fmaxf(m, __shfl_xor_sync(0xffffffffu, m, off));
    const int w = tid >> 5, l = tid & 31;
    if (l == 0) red[w] = m;
    __syncthreads();
    if (w == 0 && l < 16) {
        m = red[l];
        #pragma unroll
        for (int off = 8; off; off >>= 1)
            m = fmaxf(m, __shfl_xor_sync(0xffffffffu, m, off));
        if (l == 0) g_pmax[b][s] = m;
    }
}

// ---------------------------------------------------------------------------
// Scale pass 3: final max -> sqrt, write scale, reset exchange cells
// ---------------------------------------------------------------------------
__global__ void scale3_kernel(float* __restrict__ out)
{
    const int b = blockIdx.x, l = threadIdx.x;
    float m = (l < BPB) ? g_pmax[b][l] : 0.f;
    #pragma unroll
    for (int off = 4; off; off >>= 1)
        m = fmaxf(m, __shfl_xor_sync(0xffffffffu, m, off));
    if (l == 0) {
        float sc = __fsqrt_rn(m);        // sqrt(max) == max(sqrt): monotone
        g_scale[b] = sc;
        out[OFF_SCALE + b] = sc;
        g_ex[b].key[0] = 0; g_ex[b].key[1] = 0;
        g_ex[b].key[2] = 0; g_ex[b].key[3] = 0;
        g_ex[b].cnt = 0;                 // reset exchange (graph replays)
    }
}

// ---------------------------------------------------------------------------
// FPS: 8 CTAs per batch; warps FULLY decoupled. Per iteration each warp:
//   local argmax -> warp shfl-max -> red.max.u64 into g_key (LTS merges all
//   128 warp winners) -> red.release.add counter -> poll -> acquire-load the
//   final key -> LDG winner coords from mesh. No block barriers in the loop.
// ---------------------------------------------------------------------------
__global__ void __launch_bounds__(TH, 1)
fps_kernel(const float* __restrict__ mesh, const int* __restrict__ finit)
{
    extern __shared__ float sm[];
    float* sx = sm;
    float* sy = sm + PTS;
    float* sz = sm + 2 * PTS;

    const int blk = blockIdx.x;
    const int b = blk / BPB;
    const int s = blk - b * BPB;
    const int tid = threadIdx.x;
    const int l = tid & 31;

    const float* mb = mesh + (size_t)b * NPTS * 3;
    Exch* E = &g_ex[b];

    // stage this block's xyz slice into SMEM (SoA, one-time)
    {
        const float* gsrc = mb + (size_t)s * PTS * 3;
        for (int e = tid; e < PTS * 3; e += TH) {
            float v = gsrc[e];
            int p = e / 3;
            int c = e - 3 * p;
            sm[c * PTS + p] = v;
        }
    }

    // per-thread min-distances as int bit patterns (all values >= 0)
    int di[4 * KK];
    #pragma unroll
    for (int k = 0; k < 4 * KK; k++) di[k] = __float_as_int(1e10f);

    int fidx = finit[b];
    float cx = mb[(size_t)fidx * 3 + 0];
    float cy = mb[(size_t)fidx * 3 + 1];
    float cz = mb[(size_t)fidx * 3 + 2];

    __syncthreads();                 // smem staging visible; warps decouple now

    const ulonglong2* sxp = (const ulonglong2*)sx;
    const ulonglong2* syp = (const ulonglong2*)sy;
    const ulonglong2* szp = (const ulonglong2*)sz;

    for (int t = 0; t < NSAMP; ++t) {
        if (s == 0 && tid == 0) g_idx[b * NSAMP + t] = fidx;   // record BEFORE update
        if (t == NSAMP - 1) break;                             // uniform everywhere

        const u64 ncx = bcast2(-cx), ncy = bcast2(-cy), ncz = bcast2(-cz);

        int bvi = -1;            // int compare == float compare for nonneg floats
        int bp  = 0x7fffffff;

        #pragma unroll
        for (int k = 0; k < KK; k++) {
            const int c = k * TH + tid;
            ulonglong2 X = sxp[c];
            ulonglong2 Y = syp[c];
            ulonglong2 Z = szp[c];
            const int base = s * PTS + 4 * c;
            {   // points base, base+1
                u64 dx = add2(X.x, ncx), dy = add2(Y.x, ncy), dz = add2(Z.x, ncz);
                u64 d2 = add2(add2(mul2(dx, dx), mul2(dy, dy)), mul2(dz, dz));
                int a0, a1; unpack2(d2, a0, a1);
                int n0 = min(a0, di[4 * k + 0]); di[4 * k + 0] = n0;
                int n1 = min(a1, di[4 * k + 1]); di[4 * k + 1] = n1;
                if (n0 > bvi) { bvi = n0; bp = base; }
                if (n1 > bvi) { bvi = n1; bp = base + 1; }
            }
            {   // points base+2, base+3
                u64 dx = add2(X.y, ncx), dy = add2(Y.y, ncy), dz = add2(Z.y, ncz);
                u64 d2 = add2(add2(mul2(dx, dx), mul2(dy, dy)), mul2(dz, dz));
                int a0, a1; unpack2(d2, a0, a1);
                int n0 = min(a0, di[4 * k + 2]); di[4 * k + 2] = n0;
                int n1 = min(a1, di[4 * k + 3]); di[4 * k + 3] = n1;
                if (n0 > bvi) { bvi = n0; bp = base + 2; }
                if (n1 > bvi) { bvi = n1; bp = base + 3; }
            }
        }

        // packed key: dist desc, index asc on ties -> single u64 max
        u64 key = ((u64)(u32)bvi << 32) | (u32)(~bp);
        #pragma unroll
        for (int off = 16; off; off >>= 1) {
            u64 ok = __shfl_down_sync(0xffffffffu, key, off);
            if (ok > key) key = ok;
        }

        const int par = t & 3;
        if (l == 0) {
            st_zero64(&E->key[(t + 1) & 3]);   // recycle slot for iter t+1
            red_max64(&E->key[par], key);      // LTS merges 128 warp winners
            red_rel_add(&E->cnt, 1u);          // release-arrive
        }

        // uniform poll: lane 0 loads, whole warp loops on broadcast value
        const u32 target = (u32)(ARRIVALS * (t + 1));
        u32 c;
        do {
            c = (l == 0) ? ld_acq32(&E->cnt) : 0u;
            c = __shfl_sync(0xffffffffu, c, 0);
        } while (c < target);

        // read the merged winner, fetch its coords from mesh (L2 hit)
        u64 win = (l == 0) ? ld_acq64(&E->key[par]) : 0ull;
        win = __shfl_sync(0xffffffffu, win, 0);
        fidx = (int)(~(u32)win);
        const float* q = mb + (size_t)fidx * 3;
        cx = q[0]; cy = q[1]; cz = q[2];       // all lanes same addr -> broadcast
        // no block barrier: each warp proceeds immediately
    }
}

// ---------------------------------------------------------------------------
// Gather: sample points, normalize, emit idx as float
// ---------------------------------------------------------------------------
__global__ void __launch_bounds__(1024, 1)
gather_kernel(const float* __restrict__ mesh, float* __restrict__ out)
{
    const int b = blockIdx.x;
    const int j = threadIdx.x;
    const int i = g_idx[b * NSAMP + j];
    const float sc = g_scale[b];
    const float* q = mesh + ((size_t)b * NPTS + (size_t)i) * 3;
    const size_t o = ((size_t)b * NSAMP + j) * 3;
    out[o + 0] = __fdiv_rn(q[0], sc);
    out[o + 1] = __fdiv_rn(q[1], sc);
    out[o + 2] = __fdiv_rn(q[2], sc);
    out[OFF_IDX + b * NSAMP + j] = (float)i;   // exact: i < 2^24
}

// ---------------------------------------------------------------------------
extern "C" void kernel_launch(void* const* d_in, const int* in_sizes, int n_in,
                              void* d_out, int out_size)
{
    const float* mesh  = (const float*)d_in[0];
    const int*   finit = (const int*)d_in[1];
    float* out = (float*)d_out;

    cudaFuncSetAttribute(fps_kernel,
                         cudaFuncAttributeMaxDynamicSharedMemorySize, SMEM_BYTES);

    scale1_kernel<<<BATCH * BPB, 512>>>(mesh);
    scale2_kernel<<<BATCH * BPB, 512>>>(mesh);
    scale3_kernel<<<BATCH, 32>>>(out);                         // also resets g_ex
    fps_kernel<<<BATCH * BPB, TH, SMEM_BYTES>>>(mesh, finit);  // 128 blocks co-resident
    gather_kernel<<<BATCH, 1024>>>(mesh, out);
}

// round 10
// speedup vs baseline: 2.0178x; 2.0178x over previous
#include <cuda_runtime.h>
#include <stdint.h>

#define BATCH 16
#define NPTS  131072
#define NSAMP 1024
#define BPB   8                      // blocks per batch
#define PTS   (NPTS / BPB)           // 16384 points per block
#define TH    512                    // threads per block
#define NW    (TH / 32)              // 16 warps
#define KK    (PTS / (4 * TH))       // 8 x 4-point chunks per thread
#define SMEM_BYTES (PTS * 3 * (int)sizeof(float))   // 196608

#define OFF_SCALE (BATCH * NSAMP * 3)   // 49152
#define OFF_IDX   (OFF_SCALE + BATCH)   // 49168

typedef unsigned long long u64;
typedef unsigned int       u32;

// per-batch exchange cell: 4 key slots + arrival counter in one 128B line;
// 128B alignment so batches never share an LTS line
struct __align__(128) Exch { u64 key[4]; u32 cnt; u32 pad[23]; };

__device__ Exch  g_ex[BATCH];
__device__ int   g_idx[BATCH * NSAMP];
__device__ float g_scale[BATCH];
__device__ float g_psum[BATCH][BPB][3];
__device__ float g_pmax[BATCH][BPB];

// ---------------------------------------------------------------------------
// helpers
// ---------------------------------------------------------------------------
__device__ __forceinline__ u64 add2(u64 a, u64 b) {
    u64 d; asm("add.rn.f32x2 %0,%1,%2;" : "=l"(d) : "l"(a), "l"(b)); return d;
}
__device__ __forceinline__ u64 mul2(u64 a, u64 b) {
    u64 d; asm("mul.rn.f32x2 %0,%1,%2;" : "=l"(d) : "l"(a), "l"(b)); return d;
}
__device__ __forceinline__ void unpack2(u64 v, int& lo, int& hi) {
    asm("mov.b64 {%0,%1},%2;" : "=r"(lo), "=r"(hi) : "l"(v));
}
__device__ __forceinline__ u64 bcast2(float v) {
    u32 b = __float_as_uint(v); return ((u64)b << 32) | (u64)b;
}
__device__ __forceinline__ u32 ld_acq32(const u32* p) {
    u32 v; asm volatile("ld.acquire.gpu.global.u32 %0,[%1];" : "=r"(v) : "l"(p) : "memory");
    return v;
}
__device__ __forceinline__ u64 ld_acq64(const u64* p) {
    u64 v; asm volatile("ld.acquire.gpu.global.u64 %0,[%1];" : "=l"(v) : "l"(p) : "memory");
    return v;
}
__device__ __forceinline__ void st_zero64(u64* p) {
    asm volatile("st.relaxed.gpu.global.u64 [%0],0;" :: "l"(p) : "memory");
}
__device__ __forceinline__ void red_max64(u64* p, u64 v) {
    asm volatile("red.relaxed.gpu.global.max.u64 [%0],%1;" :: "l"(p), "l"(v) : "memory");
}
__device__ __forceinline__ void red_rel_add(u32* p, u32 v) {
    asm volatile("red.release.gpu.global.add.u32 [%0],%1;" :: "l"(p), "r"(v) : "memory");
}

// ---------------------------------------------------------------------------
// Scale pass 1: per-slice partial sums (deterministic tree)
// ---------------------------------------------------------------------------
__global__ void __launch_bounds__(512, 1)
scale1_kernel(const float* __restrict__ mesh)
{
    const int b = blockIdx.x / BPB, s = blockIdx.x % BPB, tid = threadIdx.x;
    const float* base = mesh + (size_t)b * NPTS * 3 + (size_t)s * PTS * 3;

    float sx = 0.f, sy = 0.f, sz = 0.f;
    for (int p = tid; p < PTS; p += 512) {
        const float* q = base + (size_t)p * 3;
        sx += q[0]; sy += q[1]; sz += q[2];
    }
    __shared__ float red[3][16];
    #pragma unroll
    for (int off = 16; off; off >>= 1) {
        sx += __shfl_xor_sync(0xffffffffu, sx, off);
        sy += __shfl_xor_sync(0xffffffffu, sy, off);
        sz += __shfl_xor_sync(0xffffffffu, sz, off);
    }
    const int w = tid >> 5, l = tid & 31;
    if (l == 0) { red[0][w] = sx; red[1][w] = sy; red[2][w] = sz; }
    __syncthreads();
    if (w == 0 && l < 16) {
        sx = red[0][l]; sy = red[1][l]; sz = red[2][l];
        #pragma unroll
        for (int off = 8; off; off >>= 1) {
            sx += __shfl_xor_sync(0xffffffffu, sx, off);
            sy += __shfl_xor_sync(0xffffffffu, sy, off);
            sz += __shfl_xor_sync(0xffffffffu, sz, off);
        }
        if (l == 0) {
            g_psum[b][s][0] = sx; g_psum[b][s][1] = sy; g_psum[b][s][2] = sz;
        }
    }
}

// ---------------------------------------------------------------------------
// Scale pass 2: finalize mean (fixed order), partial max of dist^2 per slice
// ---------------------------------------------------------------------------
__global__ void __launch_bounds__(512, 1)
scale2_kernel(const float* __restrict__ mesh)
{
    const int b = blockIdx.x / BPB, s = blockIdx.x % BPB, tid = threadIdx.x;

    float mx = 0.f, my = 0.f, mz = 0.f;
    #pragma unroll
    for (int i = 0; i < BPB; i++) {
        mx += g_psum[b][i][0]; my += g_psum[b][i][1]; mz += g_psum[b][i][2];
    }
    const float cx = mx * (1.0f / NPTS), cy = my * (1.0f / NPTS), cz = mz * (1.0f / NPTS);

    const float* base = mesh + (size_t)b * NPTS * 3 + (size_t)s * PTS * 3;
    float m = 0.f;
    for (int p = tid; p < PTS; p += 512) {
        const float* q = base + (size_t)p * 3;
        float dx = q[0] - cx, dy = q[1] - cy, dz = q[2] - cz;
        m = fmaxf(m, dx * dx + dy * dy + dz * dz);
    }
    __shared__ float red[16];
    #pragma unroll
    for (int off = 16; off; off >>= 1)
        m = fmaxf(m, __shfl_xor_sync(0xffffffffu, m, off));
    const int w = tid >> 5, l = tid & 31;
    if (l == 0) red[w] = m;
    __syncthreads();
    if (w == 0 && l < 16) {
        m = red[l];
        #pragma unroll
        for (int off = 8; off; off >>= 1)
            m = fmaxf(m, __shfl_xor_sync(0xffffffffu, m, off));
        if (l == 0) g_pmax[b][s] = m;
    }
}

// ---------------------------------------------------------------------------
// Scale pass 3: final max -> sqrt, write scale, reset exchange cells
// ---------------------------------------------------------------------------
__global__ void scale3_kernel(float* __restrict__ out)
{
    const int b = blockIdx.x, l = threadIdx.x;
    float m = (l < BPB) ? g_pmax[b][l] : 0.f;
    #pragma unroll
    for (int off = 4; off; off >>= 1)
        m = fmaxf(m, __shfl_xor_sync(0xffffffffu, m, off));
    if (l == 0) {
        float sc = __fsqrt_rn(m);        // sqrt(max) == max(sqrt): monotone
        g_scale[b] = sc;
        out[OFF_SCALE + b] = sc;
        g_ex[b].key[0] = 0; g_ex[b].key[1] = 0;
        g_ex[b].key[2] = 0; g_ex[b].key[3] = 0;
        g_ex[b].cnt = 0;                 // reset exchange (graph replays)
    }
}

// ---------------------------------------------------------------------------
// FPS: 8 CTAs per batch. Per iteration, per batch, the L2 exchange line sees
// ONLY: 8 red.max + 8 red.add + ~8-16 poll loads + 8 key loads (~25-40 ops),
// vs ~1000+ in earlier rounds. Merge happens inside the LTS atomic ALU.
// ---------------------------------------------------------------------------
__global__ void __launch_bounds__(TH, 1)
fps_kernel(const float* __restrict__ mesh, const int* __restrict__ finit)
{
    extern __shared__ float sm[];
    float* sx = sm;
    float* sy = sm + PTS;
    float* sz = sm + 2 * PTS;

    const int blk = blockIdx.x;
    const int b = blk / BPB;
    const int s = blk - b * BPB;
    const int tid = threadIdx.x;
    const int w = tid >> 5, l = tid & 31;

    const float* mb = mesh + (size_t)b * NPTS * 3;
    Exch* E = &g_ex[b];

    // stage this block's xyz slice into SMEM (SoA, one-time)
    {
        const float* gsrc = mb + (size_t)s * PTS * 3;
        for (int e = tid; e < PTS * 3; e += TH) {
            float v = gsrc[e];
            int p = e / 3;
            int c = e - 3 * p;
            sm[c * PTS + p] = v;
        }
    }

    // per-thread min-distances as int bit patterns (all values >= 0)
    int di[4 * KK];
    #pragma unroll
    for (int k = 0; k < 4 * KK; k++) di[k] = __float_as_int(1e10f);

    int fidx = finit[b];
    float cx = mb[(size_t)fidx * 3 + 0];
    float cy = mb[(size_t)fidx * 3 + 1];
    float cz = mb[(size_t)fidx * 3 + 2];

    __shared__ u64 skey[NW];
    __shared__ u64 swin;              // broadcast of merged winner key

    __syncthreads();

    const ulonglong2* sxp = (const ulonglong2*)sx;
    const ulonglong2* syp = (const ulonglong2*)sy;
    const ulonglong2* szp = (const ulonglong2*)sz;

    for (int t = 0; t < NSAMP; ++t) {
        if (s == 0 && tid == 0) g_idx[b * NSAMP + t] = fidx;   // record BEFORE update
        if (t == NSAMP - 1) break;

        const u64 ncx = bcast2(-cx), ncy = bcast2(-cy), ncz = bcast2(-cz);

        int bvi = -1;            // int compare == float compare for nonneg floats
        int bp  = 0x7fffffff;

        #pragma unroll
        for (int k = 0; k < KK; k++) {
            const int c = k * TH + tid;
            ulonglong2 X = sxp[c];
            ulonglong2 Y = syp[c];
            ulonglong2 Z = szp[c];
            const int base = s * PTS + 4 * c;
            {   // points base, base+1
                u64 dx = add2(X.x, ncx), dy = add2(Y.x, ncy), dz = add2(Z.x, ncz);
                u64 d2 = add2(add2(mul2(dx, dx), mul2(dy, dy)), mul2(dz, dz));
                int a0, a1; unpack2(d2, a0, a1);
                int n0 = min(a0, di[4 * k + 0]); di[4 * k + 0] = n0;
                int n1 = min(a1, di[4 * k + 1]); di[4 * k + 1] = n1;
                if (n0 > bvi) { bvi = n0; bp = base; }
                if (n1 > bvi) { bvi = n1; bp = base + 1; }
            }
            {   // points base+2, base+3
                u64 dx = add2(X.y, ncx), dy = add2(Y.y, ncy), dz = add2(Z.y, ncz);
                u64 d2 = add2(add2(mul2(dx, dx), mul2(dy, dy)), mul2(dz, dz));
                int a0, a1; unpack2(d2, a0, a1);
                int n0 = min(a0, di[4 * k + 2]); di[4 * k + 2] = n0;
                int n1 = min(a1, di[4 * k + 3]); di[4 * k + 3] = n1;
                if (n0 > bvi) { bvi = n0; bp = base + 2; }
                if (n1 > bvi) { bvi = n1; bp = base + 3; }
            }
        }

        // packed key: dist desc, index asc on ties -> single u64 max
        u64 key = ((u64)(u32)bvi << 32) | (u32)(~bp);
        #pragma unroll
        for (int off = 16; off; off >>= 1) {
            u64 ok = __shfl_down_sync(0xffffffffu, key, off);
            if (ok > key) key = ok;
        }
        if (l == 0) skey[w] = key;
        __syncthreads();

        const int par = t & 3;
        if (w == 0) {
            // level-2 reduce over 16 warp keys inside warp 0
            key = (l < NW) ? skey[l] : 0ull;
            #pragma unroll
            for (int off = 8; off; off >>= 1) {
                u64 ok = __shfl_down_sync(0xffffffffu, key, off);
                if (ok > key) key = ok;
            }
            if (l == 0) {
                st_zero64(&E->key[(t + 1) & 3]);   // recycle slot for iter t+1
                red_max64(&E->key[par], key);      // LTS merges the 8 CTA winners
                red_rel_add(&E->cnt, 1u);          // release-arrive
                // single poller per CTA
                const u32 target = (u32)(BPB * (t + 1));
                while (ld_acq32(&E->cnt) < target) { }
                swin = ld_acq64(&E->key[par]);     // merged winner -> smem
            }
        }
        __syncthreads();

        const u64 win = swin;
        fidx = (int)(~(u32)win);
        // winner coords: lane-uniform LDG (L2-resident mesh, 1 req/warp)
        const float* q = mb + (size_t)fidx * 3;
        cx = __ldg(q + 0); cy = __ldg(q + 1); cz = __ldg(q + 2);
    }
}

// ---------------------------------------------------------------------------
// Gather: sample points, normalize, emit idx as float
// ---------------------------------------------------------------------------
__global__ void __launch_bounds__(1024, 1)
gather_kernel(const float* __restrict__ mesh, float* __restrict__ out)
{
    const int b = blockIdx.x;
    const int j = threadIdx.x;
    const int i = g_idx[b * NSAMP + j];
    const float sc = g_scale[b];
    const float* q = mesh + ((size_t)b * NPTS + (size_t)i) * 3;
    const size_t o = ((size_t)b * NSAMP + j) * 3;
    out[o + 0] = __fdiv_rn(q[0], sc);
    out[o + 1] = __fdiv_rn(q[1], sc);
    out[o + 2] = __fdiv_rn(q[2], sc);
    out[OFF_IDX + b * NSAMP + j] = (float)i;   // exact: i < 2^24
}

// ---------------------------------------------------------------------------
extern "C" void kernel_launch(void* const* d_in, const int* in_sizes, int n_in,
                              void* d_out, int out_size)
{
    const float* mesh  = (const float*)d_in[0];
    const int*   finit = (const int*)d_in[1];
    float* out = (float*)d_out;

    cudaFuncSetAttribute(fps_kernel,
                         cudaFuncAttributeMaxDynamicSharedMemorySize, SMEM_BYTES);

    scale1_kernel<<<BATCH * BPB, 512>>>(mesh);
    scale2_kernel<<<BATCH * BPB, 512>>>(mesh);
    scale3_kernel<<<BATCH, 32>>>(out);                         // also resets g_ex
    fps_kernel<<<BATCH * BPB, TH, SMEM_BYTES>>>(mesh, finit);  // 128 blocks co-resident
    gather_kernel<<<BATCH, 1024>>>(mesh, out);
}